// round 5
// baseline (speedup 1.0000x reference)
#include <cuda_runtime.h>
#include <math.h>
#include <stdint.h>

// Problem constants
#define BB 4
#define TT 10
#define SS 6
#define AA 6
#define HID 512
#define LL 6
#define IMGD 128
#define NPIX 16384          // 128*128
#define NIMG_CAM 40         // B*T per camera
#define NIMG 80

#define PROW 36             // padded patch row stride (floats)
#define PCH  (34 * PROW)    // per-channel patch floats (1224)

// ---------------------------------------------------------------------------
// Scratch (static __device__ globals: allocation-free per harness rules)
// ---------------------------------------------------------------------------
__device__ float g_bufA[(size_t)NIMG * 128 * NPIX];   // max 128 ch
__device__ float g_bufB[(size_t)NIMG * 64 * NPIX];    // max 64 ch
__device__ float g_feat[NIMG_CAM * 64];               // (b*T+t, 64)
__device__ float g_h[2 * LL * BB * HID];              // double-buffered h
__device__ float g_c[LL * BB * HID];

// ---------------------------------------------------------------------------
// f32x2 packed-FMA helpers (sm_103a)
// ---------------------------------------------------------------------------
__device__ __forceinline__ unsigned long long pack2(float a, float b) {
    unsigned long long r;
    asm("mov.b64 %0, {%1, %2};" : "=l"(r) : "r"(__float_as_uint(a)), "r"(__float_as_uint(b)));
    return r;
}
__device__ __forceinline__ void unpack2(unsigned long long v, float& a, float& b) {
    unsigned int lo, hi;
    asm("mov.b64 {%0, %1}, %2;" : "=r"(lo), "=r"(hi) : "l"(v));
    a = __uint_as_float(lo); b = __uint_as_float(hi);
}
__device__ __forceinline__ void fma2(unsigned long long& d, unsigned long long a, unsigned long long b) {
    asm("fma.rn.f32x2 %0, %1, %2, %0;" : "+l"(d) : "l"(a), "l"(b));
}

// ---------------------------------------------------------------------------
// cp.async helpers
// ---------------------------------------------------------------------------
__device__ __forceinline__ void cp_async4(uint32_t smem_addr, const void* gptr, int sz) {
    asm volatile("cp.async.ca.shared.global [%0], [%1], 4, %2;\n"
                 :: "r"(smem_addr), "l"(gptr), "r"(sz));
}
__device__ __forceinline__ void cp_commit() { asm volatile("cp.async.commit_group;"); }
template<int N>
__device__ __forceinline__ void cp_wait() { asm volatile("cp.async.wait_group %0;" :: "n"(N)); }

// ---------------------------------------------------------------------------
// Stage one chunk (CB input channels) of weights + halo patch via cp.async.
// ---------------------------------------------------------------------------
template<int CIN, int CB>
__device__ __forceinline__ void stage_chunk(
    const float* __restrict__ ib, const float* __restrict__ wt,
    int g, int bx, int by, int c0,
    uint32_t ws_s, uint32_t patch_s, int tid)
{
    for (int idx = tid; idx < CB * 144; idx += 256) {
        int ci = idx / 144;
        int rem = idx - ci * 144;
        int k = rem >> 4;
        int ko = rem & 15;
        const float* src = wt + ((size_t)(g * 16 + ko) * CIN + (c0 + ci)) * 9 + k;
        cp_async4(ws_s + idx * 4, src, 4);
    }
    for (int idx = tid; idx < CB * 1156; idx += 256) {
        int ci = idx / 1156;
        int rem = idx - ci * 1156;
        int py = rem / 34;
        int px = rem - py * 34;
        int gy = by * 32 + py - 1;
        int gx = bx * 32 + px - 1;
        bool ok = ((unsigned)gy < 128u) && ((unsigned)gx < 128u);
        const float* src = ib + (size_t)(c0 + ci) * NPIX + (ok ? (gy * IMGD + gx) : 0);
        cp_async4(patch_s + (ci * PCH + py * PROW + px) * 4, src, ok ? 4 : 0);
    }
}

// ---------------------------------------------------------------------------
// Direct 3x3 SAME conv + bias + relu.
// Block: 32x32 output tile, 16 output channels, 256 threads.
// Thread: 2x2 pixel register tile x 16 ko (32 f32x2 accumulators).
// Double-buffered cp.async staging of CB-channel chunks.
// ---------------------------------------------------------------------------
template<int CIN>
__global__ void __launch_bounds__(256, 2) conv3x3_kernel(
    const float* __restrict__ in, const float* __restrict__ wt,
    const float* __restrict__ bias, float* __restrict__ out, int groups)
{
    constexpr int CB = (CIN < 8) ? CIN : 8;
    constexpr int NCHUNK = CIN / CB;

    extern __shared__ __align__(16) float smem[];
    // layout: ws[2][CB*144] then patch[2][CB*PCH]
    float* ws_base = smem;
    float* patch_base = smem + 2 * CB * 144;
    uint32_t sbase = (uint32_t)__cvta_generic_to_shared(smem);
    const uint32_t ws_off[2] = { sbase, sbase + (uint32_t)(CB * 144 * 4) };
    const uint32_t pa_off[2] = { sbase + (uint32_t)(2 * CB * 144 * 4),
                                 sbase + (uint32_t)((2 * CB * 144 + CB * PCH) * 4) };

    const int img = blockIdx.z / groups;
    const int g   = blockIdx.z % groups;
    const int tid = threadIdx.x;
    const int tx  = tid & 15;
    const int ty  = tid >> 4;
    const int bx  = (int)blockIdx.x;
    const int by  = (int)blockIdx.y;
    const int ox0 = bx * 32 + 2 * tx;
    const int oy0 = by * 32 + 2 * ty;

    const float* ib = in + (size_t)img * CIN * NPIX;

    unsigned long long acc[4][8];
    const unsigned long long z2 = pack2(0.f, 0.f);
#pragma unroll
    for (int p_ = 0; p_ < 4; p_++)
#pragma unroll
        for (int i = 0; i < 8; i++) acc[p_][i] = z2;

    // prologue: stage chunk 0 (and 1)
    stage_chunk<CIN, CB>(ib, wt, g, bx, by, 0, ws_off[0], pa_off[0], tid);
    cp_commit();
    if (NCHUNK > 1) {
        stage_chunk<CIN, CB>(ib, wt, g, bx, by, CB, ws_off[1], pa_off[1], tid);
        cp_commit();
    }

    for (int ch = 0; ch < NCHUNK; ch++) {
        const int cur = ch & 1;
        if (ch + 1 < NCHUNK) cp_wait<1>(); else cp_wait<0>();
        __syncthreads();

        const float* wchunk = ws_base + cur * CB * 144;
        const float* pchunk = patch_base + cur * CB * PCH;

#pragma unroll 2
        for (int ci = 0; ci < CB; ci++) {
            float p[4][4];
            const float* pb = pchunk + ci * PCH + (2 * ty) * PROW + 2 * tx;
#pragma unroll
            for (int r = 0; r < 4; r++) {
                float2 a = *(const float2*)(pb + r * PROW);
                float2 b = *(const float2*)(pb + r * PROW + 2);
                p[r][0] = a.x; p[r][1] = a.y; p[r][2] = b.x; p[r][3] = b.y;
            }
            const float* wk = wchunk + ci * 144;
#pragma unroll
            for (int k = 0; k < 9; k++) {
                const int ky = k / 3, kx = k - 3 * (k / 3);
                const ulonglong2* wp = (const ulonglong2*)(wk + k * 16);
                ulonglong2 w01 = wp[0];
                ulonglong2 w23 = wp[1];
                ulonglong2 w45 = wp[2];
                ulonglong2 w67 = wp[3];
#pragma unroll
                for (int p_ = 0; p_ < 4; p_++) {
                    float v = p[(p_ >> 1) + ky][(p_ & 1) + kx];
                    unsigned long long bb = pack2(v, v);
                    fma2(acc[p_][0], w01.x, bb);
                    fma2(acc[p_][1], w01.y, bb);
                    fma2(acc[p_][2], w23.x, bb);
                    fma2(acc[p_][3], w23.y, bb);
                    fma2(acc[p_][4], w45.x, bb);
                    fma2(acc[p_][5], w45.y, bb);
                    fma2(acc[p_][6], w67.x, bb);
                    fma2(acc[p_][7], w67.y, bb);
                }
            }
        }

        if (ch + 2 < NCHUNK) {
            __syncthreads();
            stage_chunk<CIN, CB>(ib, wt, g, bx, by, (ch + 2) * CB,
                                 ws_off[cur], pa_off[cur], tid);
            cp_commit();
        }
    }

    // epilogue: bias + relu + float2 stores
    float* ob = out + ((size_t)img * (groups * 16) + g * 16) * NPIX;
#pragma unroll
    for (int i = 0; i < 8; i++) {
        float b0 = bias[g * 16 + 2 * i];
        float b1 = bias[g * 16 + 2 * i + 1];
#pragma unroll
        for (int pr = 0; pr < 2; pr++) {
            float a0l, a1l, a0r, a1r;
            unpack2(acc[pr * 2 + 0][i], a0l, a1l);
            unpack2(acc[pr * 2 + 1][i], a0r, a1r);
            int row = oy0 + pr;
            float2 v0 = make_float2(fmaxf(a0l + b0, 0.f), fmaxf(a0r + b0, 0.f));
            float2 v1 = make_float2(fmaxf(a1l + b1, 0.f), fmaxf(a1r + b1, 0.f));
            *(float2*)(ob + (size_t)(2 * i) * NPIX + row * IMGD + ox0) = v0;
            *(float2*)(ob + (size_t)(2 * i + 1) * NPIX + row * IMGD + ox0) = v1;
        }
    }
}

// ---------------------------------------------------------------------------
// Spatial softmax: per (image, channel) block over 16384 positions.
// ---------------------------------------------------------------------------
__global__ void __launch_bounds__(256) sspmax_kernel(
    const float* __restrict__ conv16, float* __restrict__ feat)
{
    __shared__ float red[8];
    __shared__ float r2[3][8];

    const int id = blockIdx.x;
    const int img = id >> 4;
    const int ch = id & 15;
    const int cam = (img >= NIMG_CAM) ? 1 : 0;
    const int bt = img - cam * NIMG_CAM;
    const float* p = conv16 + ((size_t)cam * NIMG_CAM * 16 + (size_t)bt * 16 + ch) * NPIX;
    const int tid = threadIdx.x;

    float m = -1e30f;
    for (int k = tid; k < NPIX; k += 256) m = fmaxf(m, p[k]);
    for (int o = 16; o; o >>= 1) m = fmaxf(m, __shfl_xor_sync(~0u, m, o));
    if ((tid & 31) == 0) red[tid >> 5] = m;
    __syncthreads();
    if (tid < 8) {
        float v = red[tid];
        for (int o = 4; o; o >>= 1) v = fmaxf(v, __shfl_xor_sync(0xffu, v, o));
        if (tid == 0) red[0] = v;
    }
    __syncthreads();
    m = red[0];

    float se = 0.f, sx = 0.f, sy = 0.f;
    const float step = 2.f / 127.f;
    for (int k = tid; k < NPIX; k += 256) {
        float e = expf(p[k] - m);
        float px = -1.f + (float)(k & 127) * step;
        float py = -1.f + (float)(k >> 7) * step;
        se += e; sx += e * px; sy += e * py;
    }
    for (int o = 16; o; o >>= 1) {
        se += __shfl_xor_sync(~0u, se, o);
        sx += __shfl_xor_sync(~0u, sx, o);
        sy += __shfl_xor_sync(~0u, sy, o);
    }
    if ((tid & 31) == 0) { r2[0][tid >> 5] = se; r2[1][tid >> 5] = sx; r2[2][tid >> 5] = sy; }
    __syncthreads();
    if (tid == 0) {
        float a = 0.f, bx = 0.f, by = 0.f;
        for (int w = 0; w < 8; w++) { a += r2[0][w]; bx += r2[1][w]; by += r2[2][w]; }
        feat[bt * 64 + cam * 32 + 2 * ch + 0] = bx / a;
        feat[bt * 64 + cam * 32 + 2 * ch + 1] = by / a;
    }
}

// ---------------------------------------------------------------------------
// LSTM cell: one block per hidden unit j.
// 8 warps: warp = g*2 + half; each warp reads weight rows ONCE and FMAs
// against all 4 batch elements from smem (no redundant weight traffic).
// ---------------------------------------------------------------------------
__device__ __forceinline__ float sigm(float x) { return 1.f / (1.f + expf(-x)); }

__global__ void __launch_bounds__(256) lstm_cell_kernel(
    const float* __restrict__ xa, int alen, int xa_stride,
    const float* __restrict__ im,
    const float* __restrict__ wih, const float* __restrict__ whh,
    const float* __restrict__ bih, const float* __restrict__ bhh,
    const float* __restrict__ hprev, float* __restrict__ hnew,
    float* __restrict__ c)
{
    __shared__ float xs[BB][576];
    __shared__ float hs[BB][HID];
    __shared__ float part[8][BB];
    __shared__ float gs[16];

    const int inlen = alen + 64;
    const int tid = threadIdx.x;

    for (int idx = tid; idx < BB * inlen; idx += 256) {
        int b = idx / inlen;
        int k = idx - b * inlen;
        xs[b][k] = (k < alen) ? xa[b * xa_stride + k] : im[b * (TT * 64) + (k - alen)];
    }
    for (int idx = tid; idx < BB * HID; idx += 256)
        hs[idx >> 9][idx & 511] = hprev[idx];
    __syncthreads();

    const int j = blockIdx.x;
    const int warp = tid >> 5;
    const int lane = tid & 31;
    const int g = warp >> 1;
    const int half = warp & 1;
    const int row = g * HID + j;
    const int k0 = half * 32 + lane;

    float s0 = 0.f, s1 = 0.f, s2 = 0.f, s3 = 0.f;
    const float* wr = wih + (size_t)row * inlen;
#pragma unroll 4
    for (int k = k0; k < inlen; k += 64) {
        float w = wr[k];
        s0 += w * xs[0][k]; s1 += w * xs[1][k];
        s2 += w * xs[2][k]; s3 += w * xs[3][k];
    }
    const float* hr = whh + (size_t)row * HID;
#pragma unroll 4
    for (int k = k0; k < HID; k += 64) {
        float w = hr[k];
        s0 += w * hs[0][k]; s1 += w * hs[1][k];
        s2 += w * hs[2][k]; s3 += w * hs[3][k];
    }
    for (int o = 16; o; o >>= 1) {
        s0 += __shfl_xor_sync(~0u, s0, o);
        s1 += __shfl_xor_sync(~0u, s1, o);
        s2 += __shfl_xor_sync(~0u, s2, o);
        s3 += __shfl_xor_sync(~0u, s3, o);
    }
    if (lane == 0) {
        part[warp][0] = s0; part[warp][1] = s1;
        part[warp][2] = s2; part[warp][3] = s3;
    }
    __syncthreads();

    if (tid < 16) {
        int gg = tid >> 2, b = tid & 3;
        float s = part[gg * 2][b] + part[gg * 2 + 1][b]
                + bih[gg * HID + j] + bhh[gg * HID + j];
        gs[b * 4 + gg] = s;
    }
    __syncthreads();

    if (tid < BB) {
        const int b = tid;
        float gi = gs[b * 4 + 0];
        float gf = gs[b * 4 + 1];
        float gg = gs[b * 4 + 2];
        float go = gs[b * 4 + 3];
        float cold = c[b * HID + j];
        float cn = sigm(gf) * cold + sigm(gi) * tanhf(gg);
        float hn = sigm(go) * tanhf(cn);
        c[b * HID + j] = cn;
        hnew[b * HID + j] = hn;
    }
}

// ---------------------------------------------------------------------------
// Output head
// ---------------------------------------------------------------------------
__global__ void __launch_bounds__(128) out_kernel(
    const float* __restrict__ h, const float* __restrict__ im,
    const float* __restrict__ ow, const float* __restrict__ ob,
    float* __restrict__ outp)
{
    const int b = blockIdx.x / AA;
    const int a = blockIdx.x % AA;
    const float* w = ow + a * (HID + 64);
    float s = 0.f;
    for (int k = threadIdx.x; k < HID; k += 128) s += w[k] * h[b * HID + k];
    for (int k = threadIdx.x; k < 64; k += 128) s += w[HID + k] * im[b * (TT * 64) + k];
    __shared__ float red[4];
    for (int o = 16; o; o >>= 1) s += __shfl_xor_sync(~0u, s, o);
    if ((threadIdx.x & 31) == 0) red[threadIdx.x >> 5] = s;
    __syncthreads();
    if (threadIdx.x == 0)
        outp[b * (TT * AA) + a] = red[0] + red[1] + red[2] + red[3] + ob[a];
}

__global__ void zero_state_kernel()
{
    int i = blockIdx.x * blockDim.x + threadIdx.x;
    if (i < 2 * LL * BB * HID) g_h[i] = 0.f;
    if (i < LL * BB * HID) g_c[i] = 0.f;
}

// ---------------------------------------------------------------------------
// Launch
// ---------------------------------------------------------------------------
extern "C" void kernel_launch(void* const* d_in, const int* in_sizes, int n_in,
                              void* d_out, int out_size)
{
    (void)in_sizes; (void)n_in; (void)out_size;

    const float* states = (const float*)d_in[2];
    const float* wih0 = (const float*)d_in[19];
    const float* whh0 = (const float*)d_in[20];
    const float* bih0 = (const float*)d_in[21];
    const float* bhh0 = (const float*)d_in[22];
    const float* wih_r = (const float*)d_in[23];
    const float* whh_r = (const float*)d_in[24];
    const float* bih_r = (const float*)d_in[25];
    const float* bhh_r = (const float*)d_in[26];
    const float* out_w = (const float*)d_in[27];
    const float* out_b = (const float*)d_in[28];
    float* outp = (float*)d_out;

    float* bufA; cudaGetSymbolAddress((void**)&bufA, g_bufA);
    float* bufB; cudaGetSymbolAddress((void**)&bufB, g_bufB);
    float* feat; cudaGetSymbolAddress((void**)&feat, g_feat);
    float* hbuf; cudaGetSymbolAddress((void**)&hbuf, g_h);
    float* cbuf; cudaGetSymbolAddress((void**)&cbuf, g_c);

    // dynamic smem sizes: 2*(CB*144 + CB*PCH)*4 bytes
    const int smem3   = 2 * (3 * 144 + 3 * PCH) * 4;    // 32832
    const int smem8   = 2 * (8 * 144 + 8 * PCH) * 4;    // 87552
    cudaFuncSetAttribute(conv3x3_kernel<3>,   cudaFuncAttributeMaxDynamicSharedMemorySize, smem3);
    cudaFuncSetAttribute(conv3x3_kernel<32>,  cudaFuncAttributeMaxDynamicSharedMemorySize, smem8);
    cudaFuncSetAttribute(conv3x3_kernel<64>,  cudaFuncAttributeMaxDynamicSharedMemorySize, smem8);
    cudaFuncSetAttribute(conv3x3_kernel<128>, cudaFuncAttributeMaxDynamicSharedMemorySize, smem8);

    zero_state_kernel<<<96, 256>>>();

    for (int cam = 0; cam < 2; cam++) {
        const float* img = (const float*)d_in[cam];
        const float* w0 = (const float*)d_in[3 + 8 * cam];
        const float* b0 = (const float*)d_in[4 + 8 * cam];
        const float* w1 = (const float*)d_in[5 + 8 * cam];
        const float* b1 = (const float*)d_in[6 + 8 * cam];
        const float* w2 = (const float*)d_in[7 + 8 * cam];
        const float* b2 = (const float*)d_in[8 + 8 * cam];
        const float* w3 = (const float*)d_in[9 + 8 * cam];
        const float* b3 = (const float*)d_in[10 + 8 * cam];

        float* a32  = bufA + (size_t)cam * NIMG_CAM * 32 * NPIX;
        float* b64  = bufB + (size_t)cam * NIMG_CAM * 64 * NPIX;
        float* a128 = bufA + (size_t)cam * NIMG_CAM * 128 * NPIX;
        float* b16  = bufB + (size_t)cam * NIMG_CAM * 16 * NPIX;

        conv3x3_kernel<3>  <<<dim3(4, 4, NIMG_CAM * 2), 256, smem3>>>(img, w0, b0, a32, 2);
        conv3x3_kernel<32> <<<dim3(4, 4, NIMG_CAM * 4), 256, smem8>>>(a32, w1, b1, b64, 4);
        conv3x3_kernel<64> <<<dim3(4, 4, NIMG_CAM * 8), 256, smem8>>>(b64, w2, b2, a128, 8);
        conv3x3_kernel<128><<<dim3(4, 4, NIMG_CAM * 1), 256, smem8>>>(a128, w3, b3, b16, 1);
    }

    sspmax_kernel<<<NIMG * 16, 256>>>(bufB, feat);

    const int half = LL * BB * HID;
    for (int t = 0; t < TT; t++) {
        float* hprev = hbuf + (t & 1) * half;
        float* hcur  = hbuf + (1 - (t & 1)) * half;
        const float* im_t = feat + t * 64;

        lstm_cell_kernel<<<HID, 256>>>(
            states + t * SS, SS, TT * SS, im_t,
            wih0, whh0, bih0, bhh0,
            hprev + 0, hcur + 0, cbuf + 0);

        for (int l = 1; l < LL; l++) {
            lstm_cell_kernel<<<HID, 256>>>(
                hcur + (size_t)(l - 1) * BB * HID, HID, HID, im_t,
                wih_r + (size_t)(l - 1) * 4 * HID * (HID + 64),
                whh_r + (size_t)(l - 1) * 4 * HID * HID,
                bih_r + (size_t)(l - 1) * 4 * HID,
                bhh_r + (size_t)(l - 1) * 4 * HID,
                hprev + (size_t)l * BB * HID,
                hcur + (size_t)l * BB * HID,
                cbuf + (size_t)l * BB * HID);
        }

        out_kernel<<<BB * AA, 128>>>(
            hcur + (size_t)(LL - 1) * BB * HID, im_t, out_w, out_b, outp + t * AA);
    }
}

// round 6
// speedup vs baseline: 1.0035x; 1.0035x over previous
#include <cuda_runtime.h>
#include <math.h>
#include <stdint.h>

// Problem constants
#define BB 4
#define TT 10
#define SS 6
#define AA 6
#define HID 512
#define LL 6
#define IMGD 128
#define NPIX 16384          // 128*128
#define NIMG_CAM 40         // B*T per camera
#define NIMG 80

#define PROW 36             // padded patch row stride (floats)
#define PCH  (34 * PROW)    // per-channel patch floats (1224)

// ---------------------------------------------------------------------------
// Scratch (static __device__ globals: allocation-free per harness rules)
// ---------------------------------------------------------------------------
__device__ float g_bufA[(size_t)NIMG * 128 * NPIX];   // max 128 ch
__device__ float g_bufB[(size_t)NIMG * 64 * NPIX];    // max 64 ch
__device__ float g_feat[NIMG_CAM * 64];               // (b*T+t, 64)
__device__ float g_h[2 * LL * BB * HID];              // double-buffered h
__device__ float g_c[LL * BB * HID];

// ---------------------------------------------------------------------------
// f32x2 packed-FMA helpers (sm_103a)
// ---------------------------------------------------------------------------
__device__ __forceinline__ unsigned long long pack2(float a, float b) {
    unsigned long long r;
    asm("mov.b64 %0, {%1, %2};" : "=l"(r) : "r"(__float_as_uint(a)), "r"(__float_as_uint(b)));
    return r;
}
__device__ __forceinline__ void unpack2(unsigned long long v, float& a, float& b) {
    unsigned int lo, hi;
    asm("mov.b64 {%0, %1}, %2;" : "=r"(lo), "=r"(hi) : "l"(v));
    a = __uint_as_float(lo); b = __uint_as_float(hi);
}
__device__ __forceinline__ void fma2(unsigned long long& d, unsigned long long a, unsigned long long b) {
    asm("fma.rn.f32x2 %0, %1, %2, %0;" : "+l"(d) : "l"(a), "l"(b));
}

// ---------------------------------------------------------------------------
// cp.async helpers
// ---------------------------------------------------------------------------
__device__ __forceinline__ void cp_async4(uint32_t smem_addr, const void* gptr, int sz) {
    asm volatile("cp.async.ca.shared.global [%0], [%1], 4, %2;\n"
                 :: "r"(smem_addr), "l"(gptr), "r"(sz));
}
__device__ __forceinline__ void cp_commit() { asm volatile("cp.async.commit_group;"); }
template<int N>
__device__ __forceinline__ void cp_wait() { asm volatile("cp.async.wait_group %0;" :: "n"(N)); }

// ---------------------------------------------------------------------------
// Stage one chunk (CB input channels) of weights + halo patch via cp.async.
// ---------------------------------------------------------------------------
template<int CIN, int CB>
__device__ __forceinline__ void stage_chunk(
    const float* __restrict__ ib, const float* __restrict__ wt,
    int g, int bx, int by, int c0,
    uint32_t ws_s, uint32_t patch_s, int tid)
{
    for (int idx = tid; idx < CB * 144; idx += 256) {
        int ci = idx / 144;
        int rem = idx - ci * 144;
        int k = rem >> 4;
        int ko = rem & 15;
        const float* src = wt + ((size_t)(g * 16 + ko) * CIN + (c0 + ci)) * 9 + k;
        cp_async4(ws_s + idx * 4, src, 4);
    }
    for (int idx = tid; idx < CB * 1156; idx += 256) {
        int ci = idx / 1156;
        int rem = idx - ci * 1156;
        int py = rem / 34;
        int px = rem - py * 34;
        int gy = by * 32 + py - 1;
        int gx = bx * 32 + px - 1;
        bool ok = ((unsigned)gy < 128u) && ((unsigned)gx < 128u);
        const float* src = ib + (size_t)(c0 + ci) * NPIX + (ok ? (gy * IMGD + gx) : 0);
        cp_async4(patch_s + (ci * PCH + py * PROW + px) * 4, src, ok ? 4 : 0);
    }
}

// ---------------------------------------------------------------------------
// Direct 3x3 SAME conv + bias + relu.
// Block: 32x32 output tile, 16 output channels, 256 threads.
// Thread: 2x2 pixel register tile x 16 ko (32 f32x2 accumulators).
// Double-buffered cp.async staging of CB-channel chunks.
// ---------------------------------------------------------------------------
template<int CIN>
__global__ void __launch_bounds__(256, 2) conv3x3_kernel(
    const float* __restrict__ in, const float* __restrict__ wt,
    const float* __restrict__ bias, float* __restrict__ out, int groups)
{
    constexpr int CB = (CIN < 8) ? CIN : 8;
    constexpr int NCHUNK = CIN / CB;

    extern __shared__ __align__(16) float smem[];
    // layout: ws[2][CB*144] then patch[2][CB*PCH]
    float* ws_base = smem;
    float* patch_base = smem + 2 * CB * 144;
    uint32_t sbase = (uint32_t)__cvta_generic_to_shared(smem);
    const uint32_t ws_off[2] = { sbase, sbase + (uint32_t)(CB * 144 * 4) };
    const uint32_t pa_off[2] = { sbase + (uint32_t)(2 * CB * 144 * 4),
                                 sbase + (uint32_t)((2 * CB * 144 + CB * PCH) * 4) };

    const int img = blockIdx.z / groups;
    const int g   = blockIdx.z % groups;
    const int tid = threadIdx.x;
    const int tx  = tid & 15;
    const int ty  = tid >> 4;
    const int bx  = (int)blockIdx.x;
    const int by  = (int)blockIdx.y;
    const int ox0 = bx * 32 + 2 * tx;
    const int oy0 = by * 32 + 2 * ty;

    const float* ib = in + (size_t)img * CIN * NPIX;

    unsigned long long acc[4][8];
    const unsigned long long z2 = pack2(0.f, 0.f);
#pragma unroll
    for (int p_ = 0; p_ < 4; p_++)
#pragma unroll
        for (int i = 0; i < 8; i++) acc[p_][i] = z2;

    // prologue: stage chunk 0 (and 1)
    stage_chunk<CIN, CB>(ib, wt, g, bx, by, 0, ws_off[0], pa_off[0], tid);
    cp_commit();
    if (NCHUNK > 1) {
        stage_chunk<CIN, CB>(ib, wt, g, bx, by, CB, ws_off[1], pa_off[1], tid);
        cp_commit();
    }

    for (int ch = 0; ch < NCHUNK; ch++) {
        const int cur = ch & 1;
        if (ch + 1 < NCHUNK) cp_wait<1>(); else cp_wait<0>();
        __syncthreads();

        const float* wchunk = ws_base + cur * CB * 144;
        const float* pchunk = patch_base + cur * CB * PCH;

#pragma unroll 2
        for (int ci = 0; ci < CB; ci++) {
            float p[4][4];
            const float* pb = pchunk + ci * PCH + (2 * ty) * PROW + 2 * tx;
#pragma unroll
            for (int r = 0; r < 4; r++) {
                float2 a = *(const float2*)(pb + r * PROW);
                float2 b = *(const float2*)(pb + r * PROW + 2);
                p[r][0] = a.x; p[r][1] = a.y; p[r][2] = b.x; p[r][3] = b.y;
            }
            const float* wk = wchunk + ci * 144;
#pragma unroll
            for (int k = 0; k < 9; k++) {
                const int ky = k / 3, kx = k - 3 * (k / 3);
                const ulonglong2* wp = (const ulonglong2*)(wk + k * 16);
                ulonglong2 w01 = wp[0];
                ulonglong2 w23 = wp[1];
                ulonglong2 w45 = wp[2];
                ulonglong2 w67 = wp[3];
#pragma unroll
                for (int p_ = 0; p_ < 4; p_++) {
                    float v = p[(p_ >> 1) + ky][(p_ & 1) + kx];
                    unsigned long long bb = pack2(v, v);
                    fma2(acc[p_][0], w01.x, bb);
                    fma2(acc[p_][1], w01.y, bb);
                    fma2(acc[p_][2], w23.x, bb);
                    fma2(acc[p_][3], w23.y, bb);
                    fma2(acc[p_][4], w45.x, bb);
                    fma2(acc[p_][5], w45.y, bb);
                    fma2(acc[p_][6], w67.x, bb);
                    fma2(acc[p_][7], w67.y, bb);
                }
            }
        }

        if (ch + 2 < NCHUNK) {
            __syncthreads();
            stage_chunk<CIN, CB>(ib, wt, g, bx, by, (ch + 2) * CB,
                                 ws_off[cur], pa_off[cur], tid);
            cp_commit();
        }
    }

    // epilogue: bias + relu + float2 stores
    float* ob = out + ((size_t)img * (groups * 16) + g * 16) * NPIX;
#pragma unroll
    for (int i = 0; i < 8; i++) {
        float b0 = bias[g * 16 + 2 * i];
        float b1 = bias[g * 16 + 2 * i + 1];
#pragma unroll
        for (int pr = 0; pr < 2; pr++) {
            float a0l, a1l, a0r, a1r;
            unpack2(acc[pr * 2 + 0][i], a0l, a1l);
            unpack2(acc[pr * 2 + 1][i], a0r, a1r);
            int row = oy0 + pr;
            float2 v0 = make_float2(fmaxf(a0l + b0, 0.f), fmaxf(a0r + b0, 0.f));
            float2 v1 = make_float2(fmaxf(a1l + b1, 0.f), fmaxf(a1r + b1, 0.f));
            *(float2*)(ob + (size_t)(2 * i) * NPIX + row * IMGD + ox0) = v0;
            *(float2*)(ob + (size_t)(2 * i + 1) * NPIX + row * IMGD + ox0) = v1;
        }
    }
}

// ---------------------------------------------------------------------------
// Spatial softmax: per (image, channel) block over 16384 positions.
// ---------------------------------------------------------------------------
__global__ void __launch_bounds__(256) sspmax_kernel(
    const float* __restrict__ conv16, float* __restrict__ feat)
{
    __shared__ float red[8];
    __shared__ float r2[3][8];

    const int id = blockIdx.x;
    const int img = id >> 4;
    const int ch = id & 15;
    const int cam = (img >= NIMG_CAM) ? 1 : 0;
    const int bt = img - cam * NIMG_CAM;
    const float* p = conv16 + ((size_t)cam * NIMG_CAM * 16 + (size_t)bt * 16 + ch) * NPIX;
    const int tid = threadIdx.x;

    float m = -1e30f;
    for (int k = tid; k < NPIX; k += 256) m = fmaxf(m, p[k]);
    for (int o = 16; o; o >>= 1) m = fmaxf(m, __shfl_xor_sync(~0u, m, o));
    if ((tid & 31) == 0) red[tid >> 5] = m;
    __syncthreads();
    if (tid < 8) {
        float v = red[tid];
        for (int o = 4; o; o >>= 1) v = fmaxf(v, __shfl_xor_sync(0xffu, v, o));
        if (tid == 0) red[0] = v;
    }
    __syncthreads();
    m = red[0];

    float se = 0.f, sx = 0.f, sy = 0.f;
    const float step = 2.f / 127.f;
    for (int k = tid; k < NPIX; k += 256) {
        float e = expf(p[k] - m);
        float px = -1.f + (float)(k & 127) * step;
        float py = -1.f + (float)(k >> 7) * step;
        se += e; sx += e * px; sy += e * py;
    }
    for (int o = 16; o; o >>= 1) {
        se += __shfl_xor_sync(~0u, se, o);
        sx += __shfl_xor_sync(~0u, sx, o);
        sy += __shfl_xor_sync(~0u, sy, o);
    }
    if ((tid & 31) == 0) { r2[0][tid >> 5] = se; r2[1][tid >> 5] = sx; r2[2][tid >> 5] = sy; }
    __syncthreads();
    if (tid == 0) {
        float a = 0.f, bx = 0.f, by = 0.f;
        for (int w = 0; w < 8; w++) { a += r2[0][w]; bx += r2[1][w]; by += r2[2][w]; }
        feat[bt * 64 + cam * 32 + 2 * ch + 0] = bx / a;
        feat[bt * 64 + cam * 32 + 2 * ch + 1] = by / a;
    }
}

// ---------------------------------------------------------------------------
// LSTM cell: one block per hidden unit j.
// 8 warps: warp = g*2 + half; each warp reads weight rows ONCE and FMAs
// against all 4 batch elements from smem (no redundant weight traffic).
// ---------------------------------------------------------------------------
__device__ __forceinline__ float sigm(float x) { return 1.f / (1.f + expf(-x)); }

__global__ void __launch_bounds__(256) lstm_cell_kernel(
    const float* __restrict__ xa, int alen, int xa_stride,
    const float* __restrict__ im,
    const float* __restrict__ wih, const float* __restrict__ whh,
    const float* __restrict__ bih, const float* __restrict__ bhh,
    const float* __restrict__ hprev, float* __restrict__ hnew,
    float* __restrict__ c)
{
    __shared__ float xs[BB][576];
    __shared__ float hs[BB][HID];
    __shared__ float part[8][BB];
    __shared__ float gs[16];

    const int inlen = alen + 64;
    const int tid = threadIdx.x;

    for (int idx = tid; idx < BB * inlen; idx += 256) {
        int b = idx / inlen;
        int k = idx - b * inlen;
        xs[b][k] = (k < alen) ? xa[b * xa_stride + k] : im[b * (TT * 64) + (k - alen)];
    }
    for (int idx = tid; idx < BB * HID; idx += 256)
        hs[idx >> 9][idx & 511] = hprev[idx];
    __syncthreads();

    const int j = blockIdx.x;
    const int warp = tid >> 5;
    const int lane = tid & 31;
    const int g = warp >> 1;
    const int half = warp & 1;
    const int row = g * HID + j;
    const int k0 = half * 32 + lane;

    float s0 = 0.f, s1 = 0.f, s2 = 0.f, s3 = 0.f;
    const float* wr = wih + (size_t)row * inlen;
#pragma unroll 4
    for (int k = k0; k < inlen; k += 64) {
        float w = wr[k];
        s0 += w * xs[0][k]; s1 += w * xs[1][k];
        s2 += w * xs[2][k]; s3 += w * xs[3][k];
    }
    const float* hr = whh + (size_t)row * HID;
#pragma unroll 4
    for (int k = k0; k < HID; k += 64) {
        float w = hr[k];
        s0 += w * hs[0][k]; s1 += w * hs[1][k];
        s2 += w * hs[2][k]; s3 += w * hs[3][k];
    }
    for (int o = 16; o; o >>= 1) {
        s0 += __shfl_xor_sync(~0u, s0, o);
        s1 += __shfl_xor_sync(~0u, s1, o);
        s2 += __shfl_xor_sync(~0u, s2, o);
        s3 += __shfl_xor_sync(~0u, s3, o);
    }
    if (lane == 0) {
        part[warp][0] = s0; part[warp][1] = s1;
        part[warp][2] = s2; part[warp][3] = s3;
    }
    __syncthreads();

    if (tid < 16) {
        int gg = tid >> 2, b = tid & 3;
        float s = part[gg * 2][b] + part[gg * 2 + 1][b]
                + bih[gg * HID + j] + bhh[gg * HID + j];
        gs[b * 4 + gg] = s;
    }
    __syncthreads();

    if (tid < BB) {
        const int b = tid;
        float gi = gs[b * 4 + 0];
        float gf = gs[b * 4 + 1];
        float gg = gs[b * 4 + 2];
        float go = gs[b * 4 + 3];
        float cold = c[b * HID + j];
        float cn = sigm(gf) * cold + sigm(gi) * tanhf(gg);
        float hn = sigm(go) * tanhf(cn);
        c[b * HID + j] = cn;
        hnew[b * HID + j] = hn;
    }
}

// ---------------------------------------------------------------------------
// Output head
// ---------------------------------------------------------------------------
__global__ void __launch_bounds__(128) out_kernel(
    const float* __restrict__ h, const float* __restrict__ im,
    const float* __restrict__ ow, const float* __restrict__ ob,
    float* __restrict__ outp)
{
    const int b = blockIdx.x / AA;
    const int a = blockIdx.x % AA;
    const float* w = ow + a * (HID + 64);
    float s = 0.f;
    for (int k = threadIdx.x; k < HID; k += 128) s += w[k] * h[b * HID + k];
    for (int k = threadIdx.x; k < 64; k += 128) s += w[HID + k] * im[b * (TT * 64) + k];
    __shared__ float red[4];
    for (int o = 16; o; o >>= 1) s += __shfl_xor_sync(~0u, s, o);
    if ((threadIdx.x & 31) == 0) red[threadIdx.x >> 5] = s;
    __syncthreads();
    if (threadIdx.x == 0)
        outp[b * (TT * AA) + a] = red[0] + red[1] + red[2] + red[3] + ob[a];
}

__global__ void zero_state_kernel()
{
    int i = blockIdx.x * blockDim.x + threadIdx.x;
    if (i < 2 * LL * BB * HID) g_h[i] = 0.f;
    if (i < LL * BB * HID) g_c[i] = 0.f;
}

// ---------------------------------------------------------------------------
// Launch
// ---------------------------------------------------------------------------
extern "C" void kernel_launch(void* const* d_in, const int* in_sizes, int n_in,
                              void* d_out, int out_size)
{
    (void)in_sizes; (void)n_in; (void)out_size;

    const float* states = (const float*)d_in[2];
    const float* wih0 = (const float*)d_in[19];
    const float* whh0 = (const float*)d_in[20];
    const float* bih0 = (const float*)d_in[21];
    const float* bhh0 = (const float*)d_in[22];
    const float* wih_r = (const float*)d_in[23];
    const float* whh_r = (const float*)d_in[24];
    const float* bih_r = (const float*)d_in[25];
    const float* bhh_r = (const float*)d_in[26];
    const float* out_w = (const float*)d_in[27];
    const float* out_b = (const float*)d_in[28];
    float* outp = (float*)d_out;

    float* bufA; cudaGetSymbolAddress((void**)&bufA, g_bufA);
    float* bufB; cudaGetSymbolAddress((void**)&bufB, g_bufB);
    float* feat; cudaGetSymbolAddress((void**)&feat, g_feat);
    float* hbuf; cudaGetSymbolAddress((void**)&hbuf, g_h);
    float* cbuf; cudaGetSymbolAddress((void**)&cbuf, g_c);

    // dynamic smem sizes: 2*(CB*144 + CB*PCH)*4 bytes
    const int smem3   = 2 * (3 * 144 + 3 * PCH) * 4;    // 32832
    const int smem8   = 2 * (8 * 144 + 8 * PCH) * 4;    // 87552
    cudaFuncSetAttribute(conv3x3_kernel<3>,   cudaFuncAttributeMaxDynamicSharedMemorySize, smem3);
    cudaFuncSetAttribute(conv3x3_kernel<32>,  cudaFuncAttributeMaxDynamicSharedMemorySize, smem8);
    cudaFuncSetAttribute(conv3x3_kernel<64>,  cudaFuncAttributeMaxDynamicSharedMemorySize, smem8);
    cudaFuncSetAttribute(conv3x3_kernel<128>, cudaFuncAttributeMaxDynamicSharedMemorySize, smem8);

    zero_state_kernel<<<96, 256>>>();

    for (int cam = 0; cam < 2; cam++) {
        const float* img = (const float*)d_in[cam];
        const float* w0 = (const float*)d_in[3 + 8 * cam];
        const float* b0 = (const float*)d_in[4 + 8 * cam];
        const float* w1 = (const float*)d_in[5 + 8 * cam];
        const float* b1 = (const float*)d_in[6 + 8 * cam];
        const float* w2 = (const float*)d_in[7 + 8 * cam];
        const float* b2 = (const float*)d_in[8 + 8 * cam];
        const float* w3 = (const float*)d_in[9 + 8 * cam];
        const float* b3 = (const float*)d_in[10 + 8 * cam];

        float* a32  = bufA + (size_t)cam * NIMG_CAM * 32 * NPIX;
        float* b64  = bufB + (size_t)cam * NIMG_CAM * 64 * NPIX;
        float* a128 = bufA + (size_t)cam * NIMG_CAM * 128 * NPIX;
        float* b16  = bufB + (size_t)cam * NIMG_CAM * 16 * NPIX;

        conv3x3_kernel<3>  <<<dim3(4, 4, NIMG_CAM * 2), 256, smem3>>>(img, w0, b0, a32, 2);
        conv3x3_kernel<32> <<<dim3(4, 4, NIMG_CAM * 4), 256, smem8>>>(a32, w1, b1, b64, 4);
        conv3x3_kernel<64> <<<dim3(4, 4, NIMG_CAM * 8), 256, smem8>>>(b64, w2, b2, a128, 8);
        conv3x3_kernel<128><<<dim3(4, 4, NIMG_CAM * 1), 256, smem8>>>(a128, w3, b3, b16, 1);
    }

    sspmax_kernel<<<NIMG * 16, 256>>>(bufB, feat);

    const int half = LL * BB * HID;
    for (int t = 0; t < TT; t++) {
        float* hprev = hbuf + (t & 1) * half;
        float* hcur  = hbuf + (1 - (t & 1)) * half;
        const float* im_t = feat + t * 64;

        lstm_cell_kernel<<<HID, 256>>>(
            states + t * SS, SS, TT * SS, im_t,
            wih0, whh0, bih0, bhh0,
            hprev + 0, hcur + 0, cbuf + 0);

        for (int l = 1; l < LL; l++) {
            lstm_cell_kernel<<<HID, 256>>>(
                hcur + (size_t)(l - 1) * BB * HID, HID, HID, im_t,
                wih_r + (size_t)(l - 1) * 4 * HID * (HID + 64),
                whh_r + (size_t)(l - 1) * 4 * HID * HID,
                bih_r + (size_t)(l - 1) * 4 * HID,
                bhh_r + (size_t)(l - 1) * 4 * HID,
                hprev + (size_t)l * BB * HID,
                hcur + (size_t)l * BB * HID,
                cbuf + (size_t)l * BB * HID);
        }

        out_kernel<<<BB * AA, 128>>>(
            hcur + (size_t)(LL - 1) * BB * HID, im_t, out_w, out_b, outp + t * AA);
    }
}

// round 7
// speedup vs baseline: 1.9039x; 1.8971x over previous
#include <cuda_runtime.h>
#include <math.h>
#include <stdint.h>

// Problem constants
#define BB 4
#define TT 10
#define SS 6
#define AA 6
#define HID 512
#define LL 6
#define IMGD 128
#define NPIX 16384          // 128*128
#define NIMG_CAM 40         // B*T per camera
#define NIMG 80

#define PROW 36             // padded patch row stride (floats)
#define PCH  (34 * PROW)    // per-channel patch floats (1224)

// ---------------------------------------------------------------------------
// Scratch (static __device__ globals: allocation-free per harness rules)
// ---------------------------------------------------------------------------
__device__ float g_bufA[(size_t)NIMG * 128 * NPIX];   // max 128 ch
__device__ float g_bufB[(size_t)NIMG * 64 * NPIX];    // max 64 ch
__device__ float g_feat[NIMG_CAM * 64];               // (b*T+t, 64)
__device__ float g_h[2 * LL * BB * HID];              // double-buffered h
__device__ float g_c[LL * BB * HID];

// ---------------------------------------------------------------------------
// f32x2 packed-FMA helpers (layer-1 fp32 conv)
// ---------------------------------------------------------------------------
__device__ __forceinline__ unsigned long long pack2(float a, float b) {
    unsigned long long r;
    asm("mov.b64 %0, {%1, %2};" : "=l"(r) : "r"(__float_as_uint(a)), "r"(__float_as_uint(b)));
    return r;
}
__device__ __forceinline__ void unpack2(unsigned long long v, float& a, float& b) {
    unsigned int lo, hi;
    asm("mov.b64 {%0, %1}, %2;" : "=r"(lo), "=r"(hi) : "l"(v));
    a = __uint_as_float(lo); b = __uint_as_float(hi);
}
__device__ __forceinline__ void fma2(unsigned long long& d, unsigned long long a, unsigned long long b) {
    asm("fma.rn.f32x2 %0, %1, %2, %0;" : "+l"(d) : "l"(a), "l"(b));
}

// ---------------------------------------------------------------------------
// cp.async helpers
// ---------------------------------------------------------------------------
__device__ __forceinline__ void cp_async4(uint32_t smem_addr, const void* gptr, int sz) {
    asm volatile("cp.async.ca.shared.global [%0], [%1], 4, %2;\n"
                 :: "r"(smem_addr), "l"(gptr), "r"(sz));
}
__device__ __forceinline__ void cp_commit() { asm volatile("cp.async.commit_group;"); }
template<int N>
__device__ __forceinline__ void cp_wait() { asm volatile("cp.async.wait_group %0;" :: "n"(N)); }

// ---------------------------------------------------------------------------
// tf32 mma m16n8k8 (row.col), fp32 accumulate
// ---------------------------------------------------------------------------
__device__ __forceinline__ void mma_tf32(float* d, const float* a, const float* b) {
    asm volatile(
        "mma.sync.aligned.m16n8k8.row.col.f32.tf32.tf32.f32 "
        "{%0,%1,%2,%3}, {%4,%5,%6,%7}, {%8,%9}, {%0,%1,%2,%3};"
        : "+f"(d[0]), "+f"(d[1]), "+f"(d[2]), "+f"(d[3])
        : "r"(__float_as_uint(a[0])), "r"(__float_as_uint(a[1])),
          "r"(__float_as_uint(a[2])), "r"(__float_as_uint(a[3])),
          "r"(__float_as_uint(b[0])), "r"(__float_as_uint(b[1])));
}

// ---------------------------------------------------------------------------
// Stage one chunk (CB input channels) of weights + halo patch via cp.async.
// ws layout: [(ci*9+k)*16+ko]; patch layout: [ci][34][PROW]
// ---------------------------------------------------------------------------
template<int CIN, int CB>
__device__ __forceinline__ void stage_chunk(
    const float* __restrict__ ib, const float* __restrict__ wt,
    int g, int bx, int by, int c0,
    uint32_t ws_s, uint32_t patch_s, int tid)
{
    for (int idx = tid; idx < CB * 144; idx += 256) {
        int ci = idx / 144;
        int rem = idx - ci * 144;
        int k = rem >> 4;
        int ko = rem & 15;
        const float* src = wt + ((size_t)(g * 16 + ko) * CIN + (c0 + ci)) * 9 + k;
        cp_async4(ws_s + idx * 4, src, 4);
    }
    for (int idx = tid; idx < CB * 1156; idx += 256) {
        int ci = idx / 1156;
        int rem = idx - ci * 1156;
        int py = rem / 34;
        int px = rem - py * 34;
        int gy = by * 32 + py - 1;
        int gx = bx * 32 + px - 1;
        bool ok = ((unsigned)gy < 128u) && ((unsigned)gx < 128u);
        const float* src = ib + (size_t)(c0 + ci) * NPIX + (ok ? (gy * IMGD + gx) : 0);
        cp_async4(patch_s + (ci * PCH + py * PROW + px) * 4, src, ok ? 4 : 0);
    }
}

// ---------------------------------------------------------------------------
// tf32 tensor-core 3x3 SAME conv + bias + relu.
// Block: 32x32 pixel tile x 16 ko, 256 threads (8 warps).
// Warp: 8 m16n8-subtiles (16 x-pixels each) x 16 ko. K = 8 ci per tap.
// Double-buffered cp.async staging of 8-channel chunks (layout unchanged).
// ---------------------------------------------------------------------------
template<int CIN>
__global__ void __launch_bounds__(256, 2) conv3x3_tf32_kernel(
    const float* __restrict__ in, const float* __restrict__ wt,
    const float* __restrict__ bias, float* __restrict__ out, int groups)
{
    constexpr int CB = 8;
    constexpr int NCHUNK = CIN / CB;

    extern __shared__ __align__(16) float smem[];
    float* ws_base = smem;                       // 2 * CB*144
    float* patch_base = smem + 2 * CB * 144;     // 2 * CB*PCH
    uint32_t sbase = (uint32_t)__cvta_generic_to_shared(smem);
    const uint32_t ws_off[2] = { sbase, sbase + (uint32_t)(CB * 144 * 4) };
    const uint32_t pa_off[2] = { sbase + (uint32_t)(2 * CB * 144 * 4),
                                 sbase + (uint32_t)((2 * CB * 144 + CB * PCH) * 4) };

    const int img = blockIdx.z / groups;
    const int grp = blockIdx.z % groups;
    const int tid = threadIdx.x;
    const int w    = tid >> 5;          // warp 0..7
    const int lane = tid & 31;
    const int lg   = lane >> 2;         // groupID 0..7
    const int tig  = lane & 3;          // thread-in-group
    const int wy   = w >> 1;            // 0..3
    const int x0   = (w & 1) * 16;
    const int bx = (int)blockIdx.x;
    const int by = (int)blockIdx.y;

    const float* ib = in + (size_t)img * CIN * NPIX;

    float d[8][2][4];
#pragma unroll
    for (int sb = 0; sb < 8; sb++)
#pragma unroll
        for (int h = 0; h < 2; h++)
#pragma unroll
            for (int i = 0; i < 4; i++) d[sb][h][i] = 0.f;

    stage_chunk<CIN, CB>(ib, wt, grp, bx, by, 0, ws_off[0], pa_off[0], tid);
    cp_commit();
    if (NCHUNK > 1) {
        stage_chunk<CIN, CB>(ib, wt, grp, bx, by, CB, ws_off[1], pa_off[1], tid);
        cp_commit();
    }

    for (int ch = 0; ch < NCHUNK; ch++) {
        const int cur = ch & 1;
        if (ch + 1 < NCHUNK) cp_wait<1>(); else cp_wait<0>();
        __syncthreads();

        const float* W = ws_base + cur * CB * 144;
        const float* P = patch_base + cur * CB * PCH;

#pragma unroll
        for (int ky = 0; ky < 3; ky++) {
#pragma unroll
            for (int kx = 0; kx < 3; kx++) {
                const int k = ky * 3 + kx;
                // B fragments: b[h][0]=W[ci=tig][k][ko=h*8+lg], b[h][1]=ci+4
                float b[2][2];
#pragma unroll
                for (int h = 0; h < 2; h++) {
                    b[h][0] = W[(tig * 9 + k) * 16 + h * 8 + lg];
                    b[h][1] = W[((tig + 4) * 9 + k) * 16 + h * 8 + lg];
                }
#pragma unroll
                for (int sb = 0; sb < 8; sb++) {
                    const int py = sb * 4 + wy + ky;
                    const int px = x0 + kx + lg;
                    const float* ap = P + py * PROW + px;
                    float a[4];
                    a[0] = ap[tig * PCH];            // row lg,   ci tig
                    a[1] = ap[tig * PCH + 8];        // row lg+8, ci tig
                    a[2] = ap[(tig + 4) * PCH];      // row lg,   ci tig+4
                    a[3] = ap[(tig + 4) * PCH + 8];  // row lg+8, ci tig+4
                    mma_tf32(d[sb][0], a, b[0]);
                    mma_tf32(d[sb][1], a, b[1]);
                }
            }
        }

        if (ch + 2 < NCHUNK) {
            __syncthreads();
            stage_chunk<CIN, CB>(ib, wt, grp, bx, by, (ch + 2) * CB,
                                 ws_off[cur], pa_off[cur], tid);
            cp_commit();
        }
    }

    // epilogue: bias + relu + scalar stores
    float* ob = out + ((size_t)img * (groups * 16) + grp * 16) * NPIX;
    const int gxa = bx * 32 + x0 + lg;
    const int gxb = gxa + 8;
#pragma unroll
    for (int h = 0; h < 2; h++) {
        const int ko0 = h * 8 + 2 * tig;
        const float bi0 = bias[grp * 16 + ko0];
        const float bi1 = bias[grp * 16 + ko0 + 1];
        float* o0 = ob + (size_t)ko0 * NPIX;
        float* o1 = ob + (size_t)(ko0 + 1) * NPIX;
#pragma unroll
        for (int sb = 0; sb < 8; sb++) {
            const int gy = by * 32 + sb * 4 + wy;
            o0[gy * IMGD + gxa] = fmaxf(d[sb][h][0] + bi0, 0.f);
            o1[gy * IMGD + gxa] = fmaxf(d[sb][h][1] + bi1, 0.f);
            o0[gy * IMGD + gxb] = fmaxf(d[sb][h][2] + bi0, 0.f);
            o1[gy * IMGD + gxb] = fmaxf(d[sb][h][3] + bi1, 0.f);
        }
    }
}

// ---------------------------------------------------------------------------
// Layer-1 fp32 conv (CIN=3): unchanged FFMA2 kernel (tiny share of FLOPs)
// ---------------------------------------------------------------------------
template<int CIN>
__global__ void __launch_bounds__(256, 2) conv3x3_kernel(
    const float* __restrict__ in, const float* __restrict__ wt,
    const float* __restrict__ bias, float* __restrict__ out, int groups)
{
    constexpr int CB = (CIN < 8) ? CIN : 8;
    constexpr int NCHUNK = CIN / CB;

    extern __shared__ __align__(16) float smem[];
    float* ws_base = smem;
    float* patch_base = smem + 2 * CB * 144;
    uint32_t sbase = (uint32_t)__cvta_generic_to_shared(smem);
    const uint32_t ws_off[2] = { sbase, sbase + (uint32_t)(CB * 144 * 4) };
    const uint32_t pa_off[2] = { sbase + (uint32_t)(2 * CB * 144 * 4),
                                 sbase + (uint32_t)((2 * CB * 144 + CB * PCH) * 4) };

    const int img = blockIdx.z / groups;
    const int g   = blockIdx.z % groups;
    const int tid = threadIdx.x;
    const int tx  = tid & 15;
    const int ty  = tid >> 4;
    const int bx  = (int)blockIdx.x;
    const int by  = (int)blockIdx.y;
    const int ox0 = bx * 32 + 2 * tx;
    const int oy0 = by * 32 + 2 * ty;

    const float* ib = in + (size_t)img * CIN * NPIX;

    unsigned long long acc[4][8];
    const unsigned long long z2 = pack2(0.f, 0.f);
#pragma unroll
    for (int p_ = 0; p_ < 4; p_++)
#pragma unroll
        for (int i = 0; i < 8; i++) acc[p_][i] = z2;

    stage_chunk<CIN, CB>(ib, wt, g, bx, by, 0, ws_off[0], pa_off[0], tid);
    cp_commit();
    if (NCHUNK > 1) {
        stage_chunk<CIN, CB>(ib, wt, g, bx, by, CB, ws_off[1], pa_off[1], tid);
        cp_commit();
    }

    for (int ch = 0; ch < NCHUNK; ch++) {
        const int cur = ch & 1;
        if (ch + 1 < NCHUNK) cp_wait<1>(); else cp_wait<0>();
        __syncthreads();

        const float* wchunk = ws_base + cur * CB * 144;
        const float* pchunk = patch_base + cur * CB * PCH;

#pragma unroll 2
        for (int ci = 0; ci < CB; ci++) {
            float p[4][4];
            const float* pb = pchunk + ci * PCH + (2 * ty) * PROW + 2 * tx;
#pragma unroll
            for (int r = 0; r < 4; r++) {
                float2 a = *(const float2*)(pb + r * PROW);
                float2 b = *(const float2*)(pb + r * PROW + 2);
                p[r][0] = a.x; p[r][1] = a.y; p[r][2] = b.x; p[r][3] = b.y;
            }
            const float* wk = wchunk + ci * 144;
#pragma unroll
            for (int k = 0; k < 9; k++) {
                const int ky = k / 3, kx = k - 3 * (k / 3);
                const ulonglong2* wp = (const ulonglong2*)(wk + k * 16);
                ulonglong2 w01 = wp[0];
                ulonglong2 w23 = wp[1];
                ulonglong2 w45 = wp[2];
                ulonglong2 w67 = wp[3];
#pragma unroll
                for (int p_ = 0; p_ < 4; p_++) {
                    float v = p[(p_ >> 1) + ky][(p_ & 1) + kx];
                    unsigned long long bb = pack2(v, v);
                    fma2(acc[p_][0], w01.x, bb);
                    fma2(acc[p_][1], w01.y, bb);
                    fma2(acc[p_][2], w23.x, bb);
                    fma2(acc[p_][3], w23.y, bb);
                    fma2(acc[p_][4], w45.x, bb);
                    fma2(acc[p_][5], w45.y, bb);
                    fma2(acc[p_][6], w67.x, bb);
                    fma2(acc[p_][7], w67.y, bb);
                }
            }
        }

        if (ch + 2 < NCHUNK) {
            __syncthreads();
            stage_chunk<CIN, CB>(ib, wt, g, bx, by, (ch + 2) * CB,
                                 ws_off[cur], pa_off[cur], tid);
            cp_commit();
        }
    }

    float* ob = out + ((size_t)img * (groups * 16) + g * 16) * NPIX;
#pragma unroll
    for (int i = 0; i < 8; i++) {
        float b0 = bias[g * 16 + 2 * i];
        float b1 = bias[g * 16 + 2 * i + 1];
#pragma unroll
        for (int pr = 0; pr < 2; pr++) {
            float a0l, a1l, a0r, a1r;
            unpack2(acc[pr * 2 + 0][i], a0l, a1l);
            unpack2(acc[pr * 2 + 1][i], a0r, a1r);
            int row = oy0 + pr;
            float2 v0 = make_float2(fmaxf(a0l + b0, 0.f), fmaxf(a0r + b0, 0.f));
            float2 v1 = make_float2(fmaxf(a1l + b1, 0.f), fmaxf(a1r + b1, 0.f));
            *(float2*)(ob + (size_t)(2 * i) * NPIX + row * IMGD + ox0) = v0;
            *(float2*)(ob + (size_t)(2 * i + 1) * NPIX + row * IMGD + ox0) = v1;
        }
    }
}

// ---------------------------------------------------------------------------
// Spatial softmax
// ---------------------------------------------------------------------------
__global__ void __launch_bounds__(256) sspmax_kernel(
    const float* __restrict__ conv16, float* __restrict__ feat)
{
    __shared__ float red[8];
    __shared__ float r2[3][8];

    const int id = blockIdx.x;
    const int img = id >> 4;
    const int ch = id & 15;
    const int cam = (img >= NIMG_CAM) ? 1 : 0;
    const int bt = img - cam * NIMG_CAM;
    const float* p = conv16 + ((size_t)cam * NIMG_CAM * 16 + (size_t)bt * 16 + ch) * NPIX;
    const int tid = threadIdx.x;

    float m = -1e30f;
    for (int k = tid; k < NPIX; k += 256) m = fmaxf(m, p[k]);
    for (int o = 16; o; o >>= 1) m = fmaxf(m, __shfl_xor_sync(~0u, m, o));
    if ((tid & 31) == 0) red[tid >> 5] = m;
    __syncthreads();
    if (tid < 8) {
        float v = red[tid];
        for (int o = 4; o; o >>= 1) v = fmaxf(v, __shfl_xor_sync(0xffu, v, o));
        if (tid == 0) red[0] = v;
    }
    __syncthreads();
    m = red[0];

    float se = 0.f, sx = 0.f, sy = 0.f;
    const float step = 2.f / 127.f;
    for (int k = tid; k < NPIX; k += 256) {
        float e = expf(p[k] - m);
        float px = -1.f + (float)(k & 127) * step;
        float py = -1.f + (float)(k >> 7) * step;
        se += e; sx += e * px; sy += e * py;
    }
    for (int o = 16; o; o >>= 1) {
        se += __shfl_xor_sync(~0u, se, o);
        sx += __shfl_xor_sync(~0u, sx, o);
        sy += __shfl_xor_sync(~0u, sy, o);
    }
    if ((tid & 31) == 0) { r2[0][tid >> 5] = se; r2[1][tid >> 5] = sx; r2[2][tid >> 5] = sy; }
    __syncthreads();
    if (tid == 0) {
        float a = 0.f, bx = 0.f, by = 0.f;
        for (int w = 0; w < 8; w++) { a += r2[0][w]; bx += r2[1][w]; by += r2[2][w]; }
        feat[bt * 64 + cam * 32 + 2 * ch + 0] = bx / a;
        feat[bt * 64 + cam * 32 + 2 * ch + 1] = by / a;
    }
}

// ---------------------------------------------------------------------------
// LSTM cell
// ---------------------------------------------------------------------------
__device__ __forceinline__ float sigm(float x) { return 1.f / (1.f + expf(-x)); }

__global__ void __launch_bounds__(256) lstm_cell_kernel(
    const float* __restrict__ xa, int alen, int xa_stride,
    const float* __restrict__ im,
    const float* __restrict__ wih, const float* __restrict__ whh,
    const float* __restrict__ bih, const float* __restrict__ bhh,
    const float* __restrict__ hprev, float* __restrict__ hnew,
    float* __restrict__ c)
{
    __shared__ float xs[BB][576];
    __shared__ float hs[BB][HID];
    __shared__ float part[8][BB];
    __shared__ float gs[16];

    const int inlen = alen + 64;
    const int tid = threadIdx.x;

    for (int idx = tid; idx < BB * inlen; idx += 256) {
        int b = idx / inlen;
        int k = idx - b * inlen;
        xs[b][k] = (k < alen) ? xa[b * xa_stride + k] : im[b * (TT * 64) + (k - alen)];
    }
    for (int idx = tid; idx < BB * HID; idx += 256)
        hs[idx >> 9][idx & 511] = hprev[idx];
    __syncthreads();

    const int j = blockIdx.x;
    const int warp = tid >> 5;
    const int lane = tid & 31;
    const int g = warp >> 1;
    const int half = warp & 1;
    const int row = g * HID + j;
    const int k0 = half * 32 + lane;

    float s0 = 0.f, s1 = 0.f, s2 = 0.f, s3 = 0.f;
    const float* wr = wih + (size_t)row * inlen;
#pragma unroll 4
    for (int k = k0; k < inlen; k += 64) {
        float w = wr[k];
        s0 += w * xs[0][k]; s1 += w * xs[1][k];
        s2 += w * xs[2][k]; s3 += w * xs[3][k];
    }
    const float* hr = whh + (size_t)row * HID;
#pragma unroll 4
    for (int k = k0; k < HID; k += 64) {
        float w = hr[k];
        s0 += w * hs[0][k]; s1 += w * hs[1][k];
        s2 += w * hs[2][k]; s3 += w * hs[3][k];
    }
    for (int o = 16; o; o >>= 1) {
        s0 += __shfl_xor_sync(~0u, s0, o);
        s1 += __shfl_xor_sync(~0u, s1, o);
        s2 += __shfl_xor_sync(~0u, s2, o);
        s3 += __shfl_xor_sync(~0u, s3, o);
    }
    if (lane == 0) {
        part[warp][0] = s0; part[warp][1] = s1;
        part[warp][2] = s2; part[warp][3] = s3;
    }
    __syncthreads();

    if (tid < 16) {
        int gg = tid >> 2, b = tid & 3;
        float s = part[gg * 2][b] + part[gg * 2 + 1][b]
                + bih[gg * HID + j] + bhh[gg * HID + j];
        gs[b * 4 + gg] = s;
    }
    __syncthreads();

    if (tid < BB) {
        const int b = tid;
        float gi = gs[b * 4 + 0];
        float gf = gs[b * 4 + 1];
        float gg = gs[b * 4 + 2];
        float go = gs[b * 4 + 3];
        float cold = c[b * HID + j];
        float cn = sigm(gf) * cold + sigm(gi) * tanhf(gg);
        float hn = sigm(go) * tanhf(cn);
        c[b * HID + j] = cn;
        hnew[b * HID + j] = hn;
    }
}

// ---------------------------------------------------------------------------
// Output head
// ---------------------------------------------------------------------------
__global__ void __launch_bounds__(128) out_kernel(
    const float* __restrict__ h, const float* __restrict__ im,
    const float* __restrict__ ow, const float* __restrict__ ob,
    float* __restrict__ outp)
{
    const int b = blockIdx.x / AA;
    const int a = blockIdx.x % AA;
    const float* w = ow + a * (HID + 64);
    float s = 0.f;
    for (int k = threadIdx.x; k < HID; k += 128) s += w[k] * h[b * HID + k];
    for (int k = threadIdx.x; k < 64; k += 128) s += w[HID + k] * im[b * (TT * 64) + k];
    __shared__ float red[4];
    for (int o = 16; o; o >>= 1) s += __shfl_xor_sync(~0u, s, o);
    if ((threadIdx.x & 31) == 0) red[threadIdx.x >> 5] = s;
    __syncthreads();
    if (threadIdx.x == 0)
        outp[b * (TT * AA) + a] = red[0] + red[1] + red[2] + red[3] + ob[a];
}

__global__ void zero_state_kernel()
{
    int i = blockIdx.x * blockDim.x + threadIdx.x;
    if (i < 2 * LL * BB * HID) g_h[i] = 0.f;
    if (i < LL * BB * HID) g_c[i] = 0.f;
}

// ---------------------------------------------------------------------------
// Launch
// ---------------------------------------------------------------------------
extern "C" void kernel_launch(void* const* d_in, const int* in_sizes, int n_in,
                              void* d_out, int out_size)
{
    (void)in_sizes; (void)n_in; (void)out_size;

    const float* states = (const float*)d_in[2];
    const float* wih0 = (const float*)d_in[19];
    const float* whh0 = (const float*)d_in[20];
    const float* bih0 = (const float*)d_in[21];
    const float* bhh0 = (const float*)d_in[22];
    const float* wih_r = (const float*)d_in[23];
    const float* whh_r = (const float*)d_in[24];
    const float* bih_r = (const float*)d_in[25];
    const float* bhh_r = (const float*)d_in[26];
    const float* out_w = (const float*)d_in[27];
    const float* out_b = (const float*)d_in[28];
    float* outp = (float*)d_out;

    float* bufA; cudaGetSymbolAddress((void**)&bufA, g_bufA);
    float* bufB; cudaGetSymbolAddress((void**)&bufB, g_bufB);
    float* feat; cudaGetSymbolAddress((void**)&feat, g_feat);
    float* hbuf; cudaGetSymbolAddress((void**)&hbuf, g_h);
    float* cbuf; cudaGetSymbolAddress((void**)&cbuf, g_c);

    const int smem3 = 2 * (3 * 144 + 3 * PCH) * 4;    // 32832
    const int smem8 = 2 * (8 * 144 + 8 * PCH) * 4;    // 87552
    cudaFuncSetAttribute(conv3x3_kernel<3>,        cudaFuncAttributeMaxDynamicSharedMemorySize, smem3);
    cudaFuncSetAttribute(conv3x3_tf32_kernel<32>,  cudaFuncAttributeMaxDynamicSharedMemorySize, smem8);
    cudaFuncSetAttribute(conv3x3_tf32_kernel<64>,  cudaFuncAttributeMaxDynamicSharedMemorySize, smem8);
    cudaFuncSetAttribute(conv3x3_tf32_kernel<128>, cudaFuncAttributeMaxDynamicSharedMemorySize, smem8);

    zero_state_kernel<<<96, 256>>>();

    for (int cam = 0; cam < 2; cam++) {
        const float* img = (const float*)d_in[cam];
        const float* w0 = (const float*)d_in[3 + 8 * cam];
        const float* b0 = (const float*)d_in[4 + 8 * cam];
        const float* w1 = (const float*)d_in[5 + 8 * cam];
        const float* b1 = (const float*)d_in[6 + 8 * cam];
        const float* w2 = (const float*)d_in[7 + 8 * cam];
        const float* b2 = (const float*)d_in[8 + 8 * cam];
        const float* w3 = (const float*)d_in[9 + 8 * cam];
        const float* b3 = (const float*)d_in[10 + 8 * cam];

        float* a32  = bufA + (size_t)cam * NIMG_CAM * 32 * NPIX;
        float* b64  = bufB + (size_t)cam * NIMG_CAM * 64 * NPIX;
        float* a128 = bufA + (size_t)cam * NIMG_CAM * 128 * NPIX;
        float* b16  = bufB + (size_t)cam * NIMG_CAM * 16 * NPIX;

        conv3x3_kernel<3>       <<<dim3(4, 4, NIMG_CAM * 2), 256, smem3>>>(img, w0, b0, a32, 2);
        conv3x3_tf32_kernel<32> <<<dim3(4, 4, NIMG_CAM * 4), 256, smem8>>>(a32, w1, b1, b64, 4);
        conv3x3_tf32_kernel<64> <<<dim3(4, 4, NIMG_CAM * 8), 256, smem8>>>(b64, w2, b2, a128, 8);
        conv3x3_tf32_kernel<128><<<dim3(4, 4, NIMG_CAM * 1), 256, smem8>>>(a128, w3, b3, b16, 1);
    }

    sspmax_kernel<<<NIMG * 16, 256>>>(bufB, feat);

    const int half = LL * BB * HID;
    for (int t = 0; t < TT; t++) {
        float* hprev = hbuf + (t & 1) * half;
        float* hcur  = hbuf + (1 - (t & 1)) * half;
        const float* im_t = feat + t * 64;

        lstm_cell_kernel<<<HID, 256>>>(
            states + t * SS, SS, TT * SS, im_t,
            wih0, whh0, bih0, bhh0,
            hprev + 0, hcur + 0, cbuf + 0);

        for (int l = 1; l < LL; l++) {
            lstm_cell_kernel<<<HID, 256>>>(
                hcur + (size_t)(l - 1) * BB * HID, HID, HID, im_t,
                wih_r + (size_t)(l - 1) * 4 * HID * (HID + 64),
                whh_r + (size_t)(l - 1) * 4 * HID * HID,
                bih_r + (size_t)(l - 1) * 4 * HID,
                bhh_r + (size_t)(l - 1) * 4 * HID,
                hprev + (size_t)l * BB * HID,
                hcur + (size_t)l * BB * HID,
                cbuf + (size_t)l * BB * HID);
        }

        out_kernel<<<BB * AA, 128>>>(
            hcur + (size_t)(LL - 1) * BB * HID, im_t, out_w, out_b, outp + t * AA);
    }
}

// round 8
// speedup vs baseline: 2.0945x; 1.1001x over previous
#include <cuda_runtime.h>
#include <math.h>
#include <stdint.h>

// Problem constants
#define BB 4
#define TT 10
#define SS 6
#define AA 6
#define HID 512
#define LL 6
#define IMGD 128
#define NPIX 16384          // 128*128
#define NIMG_CAM 40         // B*T per camera
#define NIMG 80

#define PROW 36             // padded patch row stride (floats)
#define PCH  (34 * PROW)    // per-channel patch floats (1224)

// ---------------------------------------------------------------------------
// Scratch (static __device__ globals: allocation-free per harness rules)
// ---------------------------------------------------------------------------
__device__ float g_bufA[(size_t)NIMG * 128 * NPIX];   // max 128 ch
__device__ float g_bufB[(size_t)NIMG * 64 * NPIX];    // max 64 ch
__device__ float g_feat[NIMG_CAM * 64];               // (b*T+t, 64)
__device__ float g_h[2 * LL * BB * HID];              // double-buffered h
__device__ float g_c[LL * BB * HID];

// ---------------------------------------------------------------------------
// f32x2 packed-FMA helpers (layer-1 fp32 conv)
// ---------------------------------------------------------------------------
__device__ __forceinline__ unsigned long long pack2(float a, float b) {
    unsigned long long r;
    asm("mov.b64 %0, {%1, %2};" : "=l"(r) : "r"(__float_as_uint(a)), "r"(__float_as_uint(b)));
    return r;
}
__device__ __forceinline__ void unpack2(unsigned long long v, float& a, float& b) {
    unsigned int lo, hi;
    asm("mov.b64 {%0, %1}, %2;" : "=r"(lo), "=r"(hi) : "l"(v));
    a = __uint_as_float(lo); b = __uint_as_float(hi);
}
__device__ __forceinline__ void fma2(unsigned long long& d, unsigned long long a, unsigned long long b) {
    asm("fma.rn.f32x2 %0, %1, %2, %0;" : "+l"(d) : "l"(a), "l"(b));
}

// ---------------------------------------------------------------------------
// cp.async helpers
// ---------------------------------------------------------------------------
__device__ __forceinline__ void cp_async4(uint32_t smem_addr, const void* gptr, int sz) {
    asm volatile("cp.async.ca.shared.global [%0], [%1], 4, %2;\n"
                 :: "r"(smem_addr), "l"(gptr), "r"(sz));
}
__device__ __forceinline__ void cp_commit() { asm volatile("cp.async.commit_group;"); }
template<int N>
__device__ __forceinline__ void cp_wait() { asm volatile("cp.async.wait_group %0;" :: "n"(N)); }

// ---------------------------------------------------------------------------
// tf32 mma m16n8k8 (row.col), fp32 accumulate
// ---------------------------------------------------------------------------
__device__ __forceinline__ void mma_tf32(float* d, const float* a, const float* b) {
    asm volatile(
        "mma.sync.aligned.m16n8k8.row.col.f32.tf32.tf32.f32 "
        "{%0,%1,%2,%3}, {%4,%5,%6,%7}, {%8,%9}, {%0,%1,%2,%3};"
        : "+f"(d[0]), "+f"(d[1]), "+f"(d[2]), "+f"(d[3])
        : "r"(__float_as_uint(a[0])), "r"(__float_as_uint(a[1])),
          "r"(__float_as_uint(a[2])), "r"(__float_as_uint(a[3])),
          "r"(__float_as_uint(b[0])), "r"(__float_as_uint(b[1])));
}

// ---------------------------------------------------------------------------
// Stage one chunk (CB input channels) of weights + halo patch via cp.async.
// ws layout: [(ci*9+k)*16+ko]; patch layout: [ci][34][PROW]
// ---------------------------------------------------------------------------
template<int CIN, int CB>
__device__ __forceinline__ void stage_chunk(
    const float* __restrict__ ib, const float* __restrict__ wt,
    int g, int bx, int by, int c0,
    uint32_t ws_s, uint32_t patch_s, int tid)
{
    for (int idx = tid; idx < CB * 144; idx += 256) {
        int ci = idx / 144;
        int rem = idx - ci * 144;
        int k = rem >> 4;
        int ko = rem & 15;
        const float* src = wt + ((size_t)(g * 16 + ko) * CIN + (c0 + ci)) * 9 + k;
        cp_async4(ws_s + idx * 4, src, 4);
    }
    for (int idx = tid; idx < CB * 1156; idx += 256) {
        int ci = idx / 1156;
        int rem = idx - ci * 1156;
        int py = rem / 34;
        int px = rem - py * 34;
        int gy = by * 32 + py - 1;
        int gx = bx * 32 + px - 1;
        bool ok = ((unsigned)gy < 128u) && ((unsigned)gx < 128u);
        const float* src = ib + (size_t)(c0 + ci) * NPIX + (ok ? (gy * IMGD + gx) : 0);
        cp_async4(patch_s + (ci * PCH + py * PROW + px) * 4, src, ok ? 4 : 0);
    }
}

// ---------------------------------------------------------------------------
// tf32 tensor-core 3x3 SAME conv + bias + relu.
// Block: 32x32 pixel tile x 16 ko, 256 threads (8 warps).
// Warp: 8-row band (contiguous rows) x 16 x-pixels x 16 ko.
// A fragments for 10 patch rows are loaded once per kx and reused across
// the 3 ky taps (sb + ky = row), cutting A-LDS traffic ~2.4x.
// ---------------------------------------------------------------------------
template<int CIN>
__global__ void __launch_bounds__(256, 2) conv3x3_tf32_kernel(
    const float* __restrict__ in, const float* __restrict__ wt,
    const float* __restrict__ bias, float* __restrict__ out, int groups)
{
    constexpr int CB = 8;
    constexpr int NCHUNK = CIN / CB;

    extern __shared__ __align__(16) float smem[];
    float* ws_base = smem;                       // 2 * CB*144
    float* patch_base = smem + 2 * CB * 144;     // 2 * CB*PCH
    uint32_t sbase = (uint32_t)__cvta_generic_to_shared(smem);
    const uint32_t ws_off[2] = { sbase, sbase + (uint32_t)(CB * 144 * 4) };
    const uint32_t pa_off[2] = { sbase + (uint32_t)(2 * CB * 144 * 4),
                                 sbase + (uint32_t)((2 * CB * 144 + CB * PCH) * 4) };

    const int img = blockIdx.z / groups;
    const int grp = blockIdx.z % groups;
    const int tid = threadIdx.x;
    const int w    = tid >> 5;          // warp 0..7
    const int lane = tid & 31;
    const int lg   = lane >> 2;         // groupID 0..7
    const int tig  = lane & 3;          // thread-in-group 0..3
    const int wy   = w >> 1;            // 8-row band 0..3
    const int x0   = (w & 1) * 16;
    const int bx = (int)blockIdx.x;
    const int by = (int)blockIdx.y;

    const float* ib = in + (size_t)img * CIN * NPIX;

    float d[8][2][4];
#pragma unroll
    for (int sb = 0; sb < 8; sb++)
#pragma unroll
        for (int h = 0; h < 2; h++)
#pragma unroll
            for (int i = 0; i < 4; i++) d[sb][h][i] = 0.f;

    stage_chunk<CIN, CB>(ib, wt, grp, bx, by, 0, ws_off[0], pa_off[0], tid);
    cp_commit();
    if (NCHUNK > 1) {
        stage_chunk<CIN, CB>(ib, wt, grp, bx, by, CB, ws_off[1], pa_off[1], tid);
        cp_commit();
    }

    for (int ch = 0; ch < NCHUNK; ch++) {
        const int cur = ch & 1;
        if (ch + 1 < NCHUNK) cp_wait<1>(); else cp_wait<0>();
        __syncthreads();

        const float* W = ws_base + cur * CB * 144;
        // A base: band row 0, x = x0 + lg, ci = tig / tig+4
        const float* pa = patch_base + cur * CB * PCH
                        + (wy * 8) * PROW + x0 + lg + tig * PCH;

#pragma unroll
        for (int kx = 0; kx < 3; kx++) {
            // load 10 patch rows x 4 A-frag values (conflict-free banks)
            float a[10][4];
#pragma unroll
            for (int r = 0; r < 10; r++) {
                const float* ap = pa + r * PROW + kx;
                a[r][0] = ap[0];
                a[r][1] = ap[8];
                a[r][2] = ap[4 * PCH];
                a[r][3] = ap[4 * PCH + 8];
            }
#pragma unroll
            for (int ky = 0; ky < 3; ky++) {
                const int k = ky * 3 + kx;
                float b0[2], b1[2];
                b0[0] = W[(tig * 9 + k) * 16 + lg];
                b0[1] = W[((tig + 4) * 9 + k) * 16 + lg];
                b1[0] = W[(tig * 9 + k) * 16 + 8 + lg];
                b1[1] = W[((tig + 4) * 9 + k) * 16 + 8 + lg];
#pragma unroll
                for (int sb = 0; sb < 8; sb++) {
                    mma_tf32(d[sb][0], a[sb + ky], b0);
                    mma_tf32(d[sb][1], a[sb + ky], b1);
                }
            }
        }

        if (ch + 2 < NCHUNK) {
            __syncthreads();
            stage_chunk<CIN, CB>(ib, wt, grp, bx, by, (ch + 2) * CB,
                                 ws_off[cur], pa_off[cur], tid);
            cp_commit();
        }
    }

    // epilogue: bias + relu + scalar stores
    float* ob = out + ((size_t)img * (groups * 16) + grp * 16) * NPIX;
    const int gxa = bx * 32 + x0 + lg;
    const int gxb = gxa + 8;
#pragma unroll
    for (int h = 0; h < 2; h++) {
        const int ko0 = h * 8 + 2 * tig;
        const float bi0 = bias[grp * 16 + ko0];
        const float bi1 = bias[grp * 16 + ko0 + 1];
        float* o0 = ob + (size_t)ko0 * NPIX;
        float* o1 = ob + (size_t)(ko0 + 1) * NPIX;
#pragma unroll
        for (int sb = 0; sb < 8; sb++) {
            const int gy = by * 32 + wy * 8 + sb;
            o0[gy * IMGD + gxa] = fmaxf(d[sb][h][0] + bi0, 0.f);
            o1[gy * IMGD + gxa] = fmaxf(d[sb][h][1] + bi1, 0.f);
            o0[gy * IMGD + gxb] = fmaxf(d[sb][h][2] + bi0, 0.f);
            o1[gy * IMGD + gxb] = fmaxf(d[sb][h][3] + bi1, 0.f);
        }
    }
}

// ---------------------------------------------------------------------------
// Layer-1 fp32 conv (CIN=3): FFMA2 kernel (tiny share of FLOPs)
// ---------------------------------------------------------------------------
template<int CIN>
__global__ void __launch_bounds__(256, 2) conv3x3_kernel(
    const float* __restrict__ in, const float* __restrict__ wt,
    const float* __restrict__ bias, float* __restrict__ out, int groups)
{
    constexpr int CB = (CIN < 8) ? CIN : 8;
    constexpr int NCHUNK = CIN / CB;

    extern __shared__ __align__(16) float smem[];
    float* ws_base = smem;
    float* patch_base = smem + 2 * CB * 144;
    uint32_t sbase = (uint32_t)__cvta_generic_to_shared(smem);
    const uint32_t ws_off[2] = { sbase, sbase + (uint32_t)(CB * 144 * 4) };
    const uint32_t pa_off[2] = { sbase + (uint32_t)(2 * CB * 144 * 4),
                                 sbase + (uint32_t)((2 * CB * 144 + CB * PCH) * 4) };

    const int img = blockIdx.z / groups;
    const int g   = blockIdx.z % groups;
    const int tid = threadIdx.x;
    const int tx  = tid & 15;
    const int ty  = tid >> 4;
    const int bx  = (int)blockIdx.x;
    const int by  = (int)blockIdx.y;
    const int ox0 = bx * 32 + 2 * tx;
    const int oy0 = by * 32 + 2 * ty;

    const float* ib = in + (size_t)img * CIN * NPIX;

    unsigned long long acc[4][8];
    const unsigned long long z2 = pack2(0.f, 0.f);
#pragma unroll
    for (int p_ = 0; p_ < 4; p_++)
#pragma unroll
        for (int i = 0; i < 8; i++) acc[p_][i] = z2;

    stage_chunk<CIN, CB>(ib, wt, g, bx, by, 0, ws_off[0], pa_off[0], tid);
    cp_commit();
    if (NCHUNK > 1) {
        stage_chunk<CIN, CB>(ib, wt, g, bx, by, CB, ws_off[1], pa_off[1], tid);
        cp_commit();
    }

    for (int ch = 0; ch < NCHUNK; ch++) {
        const int cur = ch & 1;
        if (ch + 1 < NCHUNK) cp_wait<1>(); else cp_wait<0>();
        __syncthreads();

        const float* wchunk = ws_base + cur * CB * 144;
        const float* pchunk = patch_base + cur * CB * PCH;

#pragma unroll 2
        for (int ci = 0; ci < CB; ci++) {
            float p[4][4];
            const float* pb = pchunk + ci * PCH + (2 * ty) * PROW + 2 * tx;
#pragma unroll
            for (int r = 0; r < 4; r++) {
                float2 a = *(const float2*)(pb + r * PROW);
                float2 b = *(const float2*)(pb + r * PROW + 2);
                p[r][0] = a.x; p[r][1] = a.y; p[r][2] = b.x; p[r][3] = b.y;
            }
            const float* wk = wchunk + ci * 144;
#pragma unroll
            for (int k = 0; k < 9; k++) {
                const int ky = k / 3, kx = k - 3 * (k / 3);
                const ulonglong2* wp = (const ulonglong2*)(wk + k * 16);
                ulonglong2 w01 = wp[0];
                ulonglong2 w23 = wp[1];
                ulonglong2 w45 = wp[2];
                ulonglong2 w67 = wp[3];
#pragma unroll
                for (int p_ = 0; p_ < 4; p_++) {
                    float v = p[(p_ >> 1) + ky][(p_ & 1) + kx];
                    unsigned long long bb = pack2(v, v);
                    fma2(acc[p_][0], w01.x, bb);
                    fma2(acc[p_][1], w01.y, bb);
                    fma2(acc[p_][2], w23.x, bb);
                    fma2(acc[p_][3], w23.y, bb);
                    fma2(acc[p_][4], w45.x, bb);
                    fma2(acc[p_][5], w45.y, bb);
                    fma2(acc[p_][6], w67.x, bb);
                    fma2(acc[p_][7], w67.y, bb);
                }
            }
        }

        if (ch + 2 < NCHUNK) {
            __syncthreads();
            stage_chunk<CIN, CB>(ib, wt, g, bx, by, (ch + 2) * CB,
                                 ws_off[cur], pa_off[cur], tid);
            cp_commit();
        }
    }

    float* ob = out + ((size_t)img * (groups * 16) + g * 16) * NPIX;
#pragma unroll
    for (int i = 0; i < 8; i++) {
        float b0 = bias[g * 16 + 2 * i];
        float b1 = bias[g * 16 + 2 * i + 1];
#pragma unroll
        for (int pr = 0; pr < 2; pr++) {
            float a0l, a1l, a0r, a1r;
            unpack2(acc[pr * 2 + 0][i], a0l, a1l);
            unpack2(acc[pr * 2 + 1][i], a0r, a1r);
            int row = oy0 + pr;
            float2 v0 = make_float2(fmaxf(a0l + b0, 0.f), fmaxf(a0r + b0, 0.f));
            float2 v1 = make_float2(fmaxf(a1l + b1, 0.f), fmaxf(a1r + b1, 0.f));
            *(float2*)(ob + (size_t)(2 * i) * NPIX + row * IMGD + ox0) = v0;
            *(float2*)(ob + (size_t)(2 * i + 1) * NPIX + row * IMGD + ox0) = v1;
        }
    }
}

// ---------------------------------------------------------------------------
// Spatial softmax
// ---------------------------------------------------------------------------
__global__ void __launch_bounds__(256) sspmax_kernel(
    const float* __restrict__ conv16, float* __restrict__ feat)
{
    __shared__ float red[8];
    __shared__ float r2[3][8];

    const int id = blockIdx.x;
    const int img = id >> 4;
    const int ch = id & 15;
    const int cam = (img >= NIMG_CAM) ? 1 : 0;
    const int bt = img - cam * NIMG_CAM;
    const float* p = conv16 + ((size_t)cam * NIMG_CAM * 16 + (size_t)bt * 16 + ch) * NPIX;
    const int tid = threadIdx.x;

    float m = -1e30f;
    for (int k = tid; k < NPIX; k += 256) m = fmaxf(m, p[k]);
    for (int o = 16; o; o >>= 1) m = fmaxf(m, __shfl_xor_sync(~0u, m, o));
    if ((tid & 31) == 0) red[tid >> 5] = m;
    __syncthreads();
    if (tid < 8) {
        float v = red[tid];
        for (int o = 4; o; o >>= 1) v = fmaxf(v, __shfl_xor_sync(0xffu, v, o));
        if (tid == 0) red[0] = v;
    }
    __syncthreads();
    m = red[0];

    float se = 0.f, sx = 0.f, sy = 0.f;
    const float step = 2.f / 127.f;
    for (int k = tid; k < NPIX; k += 256) {
        float e = expf(p[k] - m);
        float px = -1.f + (float)(k & 127) * step;
        float py = -1.f + (float)(k >> 7) * step;
        se += e; sx += e * px; sy += e * py;
    }
    for (int o = 16; o; o >>= 1) {
        se += __shfl_xor_sync(~0u, se, o);
        sx += __shfl_xor_sync(~0u, sx, o);
        sy += __shfl_xor_sync(~0u, sy, o);
    }
    if ((tid & 31) == 0) { r2[0][tid >> 5] = se; r2[1][tid >> 5] = sx; r2[2][tid >> 5] = sy; }
    __syncthreads();
    if (tid == 0) {
        float a = 0.f, bx = 0.f, by = 0.f;
        for (int w = 0; w < 8; w++) { a += r2[0][w]; bx += r2[1][w]; by += r2[2][w]; }
        feat[bt * 64 + cam * 32 + 2 * ch + 0] = bx / a;
        feat[bt * 64 + cam * 32 + 2 * ch + 1] = by / a;
    }
}

// ---------------------------------------------------------------------------
// LSTM cell
// ---------------------------------------------------------------------------
__device__ __forceinline__ float sigm(float x) { return 1.f / (1.f + expf(-x)); }

__global__ void __launch_bounds__(256) lstm_cell_kernel(
    const float* __restrict__ xa, int alen, int xa_stride,
    const float* __restrict__ im,
    const float* __restrict__ wih, const float* __restrict__ whh,
    const float* __restrict__ bih, const float* __restrict__ bhh,
    const float* __restrict__ hprev, float* __restrict__ hnew,
    float* __restrict__ c)
{
    __shared__ float xs[BB][576];
    __shared__ float hs[BB][HID];
    __shared__ float part[8][BB];
    __shared__ float gs[16];

    const int inlen = alen + 64;
    const int tid = threadIdx.x;

    for (int idx = tid; idx < BB * inlen; idx += 256) {
        int b = idx / inlen;
        int k = idx - b * inlen;
        xs[b][k] = (k < alen) ? xa[b * xa_stride + k] : im[b * (TT * 64) + (k - alen)];
    }
    for (int idx = tid; idx < BB * HID; idx += 256)
        hs[idx >> 9][idx & 511] = hprev[idx];
    __syncthreads();

    const int j = blockIdx.x;
    const int warp = tid >> 5;
    const int lane = tid & 31;
    const int g = warp >> 1;
    const int half = warp & 1;
    const int row = g * HID + j;
    const int k0 = half * 32 + lane;

    float s0 = 0.f, s1 = 0.f, s2 = 0.f, s3 = 0.f;
    const float* wr = wih + (size_t)row * inlen;
#pragma unroll 4
    for (int k = k0; k < inlen; k += 64) {
        float w = wr[k];
        s0 += w * xs[0][k]; s1 += w * xs[1][k];
        s2 += w * xs[2][k]; s3 += w * xs[3][k];
    }
    const float* hr = whh + (size_t)row * HID;
#pragma unroll 4
    for (int k = k0; k < HID; k += 64) {
        float w = hr[k];
        s0 += w * hs[0][k]; s1 += w * hs[1][k];
        s2 += w * hs[2][k]; s3 += w * hs[3][k];
    }
    for (int o = 16; o; o >>= 1) {
        s0 += __shfl_xor_sync(~0u, s0, o);
        s1 += __shfl_xor_sync(~0u, s1, o);
        s2 += __shfl_xor_sync(~0u, s2, o);
        s3 += __shfl_xor_sync(~0u, s3, o);
    }
    if (lane == 0) {
        part[warp][0] = s0; part[warp][1] = s1;
        part[warp][2] = s2; part[warp][3] = s3;
    }
    __syncthreads();

    if (tid < 16) {
        int gg = tid >> 2, b = tid & 3;
        float s = part[gg * 2][b] + part[gg * 2 + 1][b]
                + bih[gg * HID + j] + bhh[gg * HID + j];
        gs[b * 4 + gg] = s;
    }
    __syncthreads();

    if (tid < BB) {
        const int b = tid;
        float gi = gs[b * 4 + 0];
        float gf = gs[b * 4 + 1];
        float gg = gs[b * 4 + 2];
        float go = gs[b * 4 + 3];
        float cold = c[b * HID + j];
        float cn = sigm(gf) * cold + sigm(gi) * tanhf(gg);
        float hn = sigm(go) * tanhf(cn);
        c[b * HID + j] = cn;
        hnew[b * HID + j] = hn;
    }
}

// ---------------------------------------------------------------------------
// Output head
// ---------------------------------------------------------------------------
__global__ void __launch_bounds__(128) out_kernel(
    const float* __restrict__ h, const float* __restrict__ im,
    const float* __restrict__ ow, const float* __restrict__ ob,
    float* __restrict__ outp)
{
    const int b = blockIdx.x / AA;
    const int a = blockIdx.x % AA;
    const float* w = ow + a * (HID + 64);
    float s = 0.f;
    for (int k = threadIdx.x; k < HID; k += 128) s += w[k] * h[b * HID + k];
    for (int k = threadIdx.x; k < 64; k += 128) s += w[HID + k] * im[b * (TT * 64) + k];
    __shared__ float red[4];
    for (int o = 16; o; o >>= 1) s += __shfl_xor_sync(~0u, s, o);
    if ((threadIdx.x & 31) == 0) red[threadIdx.x >> 5] = s;
    __syncthreads();
    if (threadIdx.x == 0)
        outp[b * (TT * AA) + a] = red[0] + red[1] + red[2] + red[3] + ob[a];
}

__global__ void zero_state_kernel()
{
    int i = blockIdx.x * blockDim.x + threadIdx.x;
    if (i < 2 * LL * BB * HID) g_h[i] = 0.f;
    if (i < LL * BB * HID) g_c[i] = 0.f;
}

// ---------------------------------------------------------------------------
// Launch
// ---------------------------------------------------------------------------
extern "C" void kernel_launch(void* const* d_in, const int* in_sizes, int n_in,
                              void* d_out, int out_size)
{
    (void)in_sizes; (void)n_in; (void)out_size;

    const float* states = (const float*)d_in[2];
    const float* wih0 = (const float*)d_in[19];
    const float* whh0 = (const float*)d_in[20];
    const float* bih0 = (const float*)d_in[21];
    const float* bhh0 = (const float*)d_in[22];
    const float* wih_r = (const float*)d_in[23];
    const float* whh_r = (const float*)d_in[24];
    const float* bih_r = (const float*)d_in[25];
    const float* bhh_r = (const float*)d_in[26];
    const float* out_w = (const float*)d_in[27];
    const float* out_b = (const float*)d_in[28];
    float* outp = (float*)d_out;

    float* bufA; cudaGetSymbolAddress((void**)&bufA, g_bufA);
    float* bufB; cudaGetSymbolAddress((void**)&bufB, g_bufB);
    float* feat; cudaGetSymbolAddress((void**)&feat, g_feat);
    float* hbuf; cudaGetSymbolAddress((void**)&hbuf, g_h);
    float* cbuf; cudaGetSymbolAddress((void**)&cbuf, g_c);

    const int smem3 = 2 * (3 * 144 + 3 * PCH) * 4;    // 32832
    const int smem8 = 2 * (8 * 144 + 8 * PCH) * 4;    // 87552
    cudaFuncSetAttribute(conv3x3_kernel<3>,        cudaFuncAttributeMaxDynamicSharedMemorySize, smem3);
    cudaFuncSetAttribute(conv3x3_tf32_kernel<32>,  cudaFuncAttributeMaxDynamicSharedMemorySize, smem8);
    cudaFuncSetAttribute(conv3x3_tf32_kernel<64>,  cudaFuncAttributeMaxDynamicSharedMemorySize, smem8);
    cudaFuncSetAttribute(conv3x3_tf32_kernel<128>, cudaFuncAttributeMaxDynamicSharedMemorySize, smem8);

    zero_state_kernel<<<96, 256>>>();

    for (int cam = 0; cam < 2; cam++) {
        const float* img = (const float*)d_in[cam];
        const float* w0 = (const float*)d_in[3 + 8 * cam];
        const float* b0 = (const float*)d_in[4 + 8 * cam];
        const float* w1 = (const float*)d_in[5 + 8 * cam];
        const float* b1 = (const float*)d_in[6 + 8 * cam];
        const float* w2 = (const float*)d_in[7 + 8 * cam];
        const float* b2 = (const float*)d_in[8 + 8 * cam];
        const float* w3 = (const float*)d_in[9 + 8 * cam];
        const float* b3 = (const float*)d_in[10 + 8 * cam];

        float* a32  = bufA + (size_t)cam * NIMG_CAM * 32 * NPIX;
        float* b64  = bufB + (size_t)cam * NIMG_CAM * 64 * NPIX;
        float* a128 = bufA + (size_t)cam * NIMG_CAM * 128 * NPIX;
        float* b16  = bufB + (size_t)cam * NIMG_CAM * 16 * NPIX;

        conv3x3_kernel<3>       <<<dim3(4, 4, NIMG_CAM * 2), 256, smem3>>>(img, w0, b0, a32, 2);
        conv3x3_tf32_kernel<32> <<<dim3(4, 4, NIMG_CAM * 4), 256, smem8>>>(a32, w1, b1, b64, 4);
        conv3x3_tf32_kernel<64> <<<dim3(4, 4, NIMG_CAM * 8), 256, smem8>>>(b64, w2, b2, a128, 8);
        conv3x3_tf32_kernel<128><<<dim3(4, 4, NIMG_CAM * 1), 256, smem8>>>(a128, w3, b3, b16, 1);
    }

    sspmax_kernel<<<NIMG * 16, 256>>>(bufB, feat);

    const int half = LL * BB * HID;
    for (int t = 0; t < TT; t++) {
        float* hprev = hbuf + (t & 1) * half;
        float* hcur  = hbuf + (1 - (t & 1)) * half;
        const float* im_t = feat + t * 64;

        lstm_cell_kernel<<<HID, 256>>>(
            states + t * SS, SS, TT * SS, im_t,
            wih0, whh0, bih0, bhh0,
            hprev + 0, hcur + 0, cbuf + 0);

        for (int l = 1; l < LL; l++) {
            lstm_cell_kernel<<<HID, 256>>>(
                hcur + (size_t)(l - 1) * BB * HID, HID, HID, im_t,
                wih_r + (size_t)(l - 1) * 4 * HID * (HID + 64),
                whh_r + (size_t)(l - 1) * 4 * HID * HID,
                bih_r + (size_t)(l - 1) * 4 * HID,
                bhh_r + (size_t)(l - 1) * 4 * HID,
                hprev + (size_t)l * BB * HID,
                hcur + (size_t)l * BB * HID,
                cbuf + (size_t)l * BB * HID);
        }

        out_kernel<<<BB * AA, 128>>>(
            hcur + (size_t)(LL - 1) * BB * HID, im_t, out_w, out_b, outp + t * AA);
    }
}